// round 17
// baseline (speedup 1.0000x reference)
#include <cuda_runtime.h>
#include <cuda_fp16.h>
#include <cstdint>

#define NH 12
#define TT 2048
#define BB 4
#define DM 768
#define HD 64
#define MTOT (BB*TT)
#define NBH (BB*NH)
#define QSCALE 0.18033688011112042f   // log2(e)/sqrt(64)

// ---------------- global scratch (allocation-free) ----------------
__device__ __half g_Xh[MTOT*DM];                         // fp16 input
__device__ __half g_W3h[NH*192*DM];                      // [h][n=q|k|v*64+e][k]
__device__ __half g_W2Th[DM*DM];                         // [n][k], gate folded
__device__ float  g_b2[DM];
__device__ __half g_Qh[NBH*TT*HD];                       // [bh][t][e] (scale folded)
__device__ __half g_Kh[NBH*TT*HD];                       // [bh][t][e]
__device__ __half g_VTh[NBH*HD*TT];                      // [bh][e][t]
__device__ __half g_Ah[MTOT*DM];                         // attn out [8192][768]

// ---------------- helpers ----------------
__device__ __forceinline__ uint32_t smem_u32(const void* p) {
    uint32_t a;
    asm("{ .reg .u64 t; cvta.to.shared.u64 t, %1; cvt.u32.u64 %0, t; }" : "=r"(a) : "l"(p));
    return a;
}
__device__ __forceinline__ float fexp2(float x) {
    float y; asm("ex2.approx.ftz.f32 %0, %1;" : "=f"(y) : "f"(x)); return y;
}
__device__ __forceinline__ void cp16(uint32_t dst, const void* src) {
    asm volatile("cp.async.cg.shared.global [%0], [%1], 16;" :: "r"(dst), "l"(src));
}
#define CP_COMMIT() asm volatile("cp.async.commit_group;" ::: "memory")
#define CP_WAIT0()  asm volatile("cp.async.wait_group 0;" ::: "memory")
#define CP_WAIT1()  asm volatile("cp.async.wait_group 1;" ::: "memory")

__device__ __forceinline__ void ldsm4(uint32_t* r, uint32_t addr) {
    asm volatile("ldmatrix.sync.aligned.m8n8.x4.shared.b16 {%0,%1,%2,%3}, [%4];"
        : "=r"(r[0]), "=r"(r[1]), "=r"(r[2]), "=r"(r[3]) : "r"(addr));
}
__device__ __forceinline__ void mma16816(float* d, const uint32_t* a, const uint32_t* b) {
    asm volatile("mma.sync.aligned.m16n8k16.row.col.f32.f16.f16.f32 "
        "{%0,%1,%2,%3}, {%4,%5,%6,%7}, {%8,%9}, {%0,%1,%2,%3};"
        : "+f"(d[0]), "+f"(d[1]), "+f"(d[2]), "+f"(d[3])
        : "r"(a[0]), "r"(a[1]), "r"(a[2]), "r"(a[3]), "r"(b[0]), "r"(b[1]));
}
// A fragment (16x16) from row-major [m][k]
__device__ __forceinline__ void lda_frag(uint32_t* r, uint32_t sbase, int m0, int k0,
                                         int pitch, int lane) {
    uint32_t addr = sbase + (uint32_t)(((m0 + (lane & 7) + ((lane >> 3) & 1) * 8) * pitch
                                       + k0 + ((lane >> 4) & 1) * 8) * 2);
    ldsm4(r, addr);
}
// paired B fragments (two adjacent 8-n tiles, 16 k) from row-major [n][k]
__device__ __forceinline__ void ldb_frag2(uint32_t* r, uint32_t sbase, int n0, int k0,
                                          int pitch, int lane) {
    uint32_t addr = sbase + (uint32_t)(((n0 + ((lane >> 4) & 1) * 8 + (lane & 7)) * pitch
                                       + k0 + ((lane >> 3) & 1) * 8) * 2);
    ldsm4(r, addr);
}
__device__ __forceinline__ uint32_t h2pack(float a, float b) {
    __half2 h = __floats2half2_rn(a, b);
    return *(uint32_t*)&h;
}

// ---------------- merged prep (one launch) ----------------
#define PB_X  6144
#define PB_W3 13056
#define PB_W2 15360
#define PB_TOT 15363

__global__ void prep_all(const float* __restrict__ X,
                         const float* __restrict__ Wq, const float* __restrict__ Wk,
                         const float* __restrict__ Wv, const float* __restrict__ Wo,
                         const float* __restrict__ bo, const float* __restrict__ gate)
{
    int blk = blockIdx.x;
    if (blk < PB_X) {
        int idx = (blk * 256 + threadIdx.x) * 4;
        float4 v = *(const float4*)(X + idx);
        *(__half2*)(g_Xh + idx)     = __floats2half2_rn(v.x, v.y);
        *(__half2*)(g_Xh + idx + 2) = __floats2half2_rn(v.z, v.w);
    } else if (blk < PB_W3) {
        int idx = (blk - PB_X) * 256 + threadIdx.x;
        int k = idx % DM;
        int n = (idx / DM) % 192;
        int h = idx / (192*DM);
        int part = n >> 6, e = n & 63;
        const float* W = (part == 0) ? Wq : (part == 1) ? Wk : Wv;
        float v = W[((size_t)h*DM + k)*HD + e];
        if (part == 0) v *= QSCALE;
        g_W3h[idx] = __float2half_rn(v);
    } else if (blk < PB_W2) {
        int idx = (blk - PB_W3) * 256 + threadIdx.x;
        int k = idx % DM, n = idx / DM;
        int h = k >> 6, e = k & 63;
        float g = gate[h]; g = (g < 1e-6f) ? 0.0f : g;
        g_W2Th[idx] = __float2half_rn(Wo[((size_t)h*HD + e)*DM + n] * g);
    } else {
        int d = (blk - PB_W2) * 256 + threadIdx.x;
        if (d < DM) {
            float s = 0.0f;
            #pragma unroll
            for (int h = 0; h < NH; h++) {
                float g = gate[h]; g = (g < 1e-6f) ? 0.0f : g;
                s += g * bo[h*DM + d];
            }
            g_b2[d] = s;
        }
    }
}

// ============ GEMM 256m x 96n, K=768, BK=32, 256 thr, warp 64x48 ===========
// per-stage smem: Ah[256][40] @0 (20480), Bh[96][40] @20480 (7680) = 28160, x3
#define GS_AH 0u
#define GS_BH 20480u
#define G_STAGE 28160u
#define G_SMEM 84480

__device__ __forceinline__ void gemm_load_stage(
    uint32_t sb, int s, int k0, int tid,
    const __half* Ah, const __half* Bh)
{
    uint32_t base = sb + (uint32_t)s * G_STAGE;
    #pragma unroll
    for (int i = 0; i < 4; i++) {
        int f = tid + i*256;
        int r = f >> 2, c = (f & 3) * 8;
        cp16(base + GS_AH + (uint32_t)(r*80 + c*2), Ah + (size_t)r*DM + k0 + c);
    }
    #pragma unroll
    for (int i = 0; i < 2; i++) {
        int f = tid + i*256;
        if (f < 384) {
            int r = f >> 2, c = (f & 3) * 8;
            cp16(base + GS_BH + (uint32_t)(r*80 + c*2), Bh + (size_t)r*DM + k0 + c);
        }
    }
}

__device__ __forceinline__ void gemm_main(
    uint32_t sb, int tid, int lane, int WM, int WN,
    const __half* Ah, const __half* Bh,
    float acc[4][6][4])
{
    gemm_load_stage(sb, 0, 0, tid, Ah, Bh);
    CP_COMMIT();
    gemm_load_stage(sb, 1, 32, tid, Ah, Bh);
    CP_COMMIT();
    int sidx = 0;
    #pragma unroll 1
    for (int ch = 0; ch < 24; ch++) {
        CP_WAIT1();
        __syncthreads();
        if (ch + 2 < 24) {
            int sn = sidx + 2; if (sn >= 3) sn -= 3;
            gemm_load_stage(sb, sn, (ch+2)*32, tid, Ah, Bh);
            CP_COMMIT();
        }
        uint32_t base = sb + (uint32_t)sidx * G_STAGE;
        #pragma unroll
        for (int ks = 0; ks < 2; ks++) {
            int kk = ks * 16;
            uint32_t bhf[3][4];
            #pragma unroll
            for (int np = 0; np < 3; np++)
                ldb_frag2(bhf[np], base + GS_BH, WN + np*16, kk, 40, lane);
            #pragma unroll
            for (int mt = 0; mt < 4; mt++) {
                uint32_t ah[4];
                lda_frag(ah, base + GS_AH, WM + mt*16, kk, 40, lane);
                #pragma unroll
                for (int np = 0; np < 3; np++)
                    #pragma unroll
                    for (int hp = 0; hp < 2; hp++)
                        mma16816(acc[mt][np*2+hp], ah, bhf[np] + hp*2);
            }
        }
        if (++sidx >= 3) sidx = 0;
    }
    __syncthreads();
}

// ---------------- QKV projection: grid (32, 12, 2), n-split 96 -------------
__global__ void __launch_bounds__(256, 2)
qkv_mma(const float* __restrict__ bq, const float* __restrict__ bk,
        const float* __restrict__ bv)
{
    extern __shared__ __align__(16) char smc[];
    const uint32_t sb = smem_u32(smc);
    const int m0 = blockIdx.x * 256, h = blockIdx.y;
    const int n0g = blockIdx.z * 96;
    const int tid = threadIdx.x, lane = tid & 31, w = tid >> 5;
    const int WM = (w >> 1) * 64, WN = (w & 1) * 48;

    float acc[4][6][4];
    #pragma unroll
    for (int mt = 0; mt < 4; mt++)
        #pragma unroll
        for (int nt = 0; nt < 6; nt++)
            #pragma unroll
            for (int c = 0; c < 4; c++) acc[mt][nt][c] = 0.0f;

    gemm_main(sb, tid, lane, WM, WN,
              g_Xh + (size_t)m0*DM, g_W3h + (size_t)h*192*DM + (size_t)n0g*DM, acc);

    #pragma unroll
    for (int mt = 0; mt < 4; mt++)
        #pragma unroll
        for (int rh = 0; rh < 2; rh++) {
            int m = m0 + WM + mt*16 + (lane >> 2) + rh*8;
            int b = m >> 11, t = m & (TT-1);
            int bhi = b*NH + h;
            #pragma unroll
            for (int nt = 0; nt < 6; nt++) {
                int col = n0g + WN + nt*8 + (lane & 3)*2;
                int part = col >> 6, e = col & 63;
                float v0 = acc[mt][nt][rh*2 + 0];
                float v1 = acc[mt][nt][rh*2 + 1];
                if (part == 0)      { v0 += bq[h*HD+e]*QSCALE; v1 += bq[h*HD+e+1]*QSCALE; }
                else if (part == 1) { v0 += bk[h*HD+e];        v1 += bk[h*HD+e+1]; }
                else                { v0 += bv[h*HD+e];        v1 += bv[h*HD+e+1]; }
                if (part == 0) {
                    size_t off = ((size_t)bhi*TT + t)*HD + e;
                    *(__half2*)(g_Qh + off) = __floats2half2_rn(v0, v1);
                } else if (part == 1) {
                    size_t off = ((size_t)bhi*TT + t)*HD + e;
                    *(__half2*)(g_Kh + off) = __floats2half2_rn(v0, v1);
                } else {
                    size_t off = ((size_t)bhi*HD + e)*TT + t;
                    g_VTh[off]      = __float2half_rn(v0);
                    g_VTh[off + TT] = __float2half_rn(v1);
                }
            }
        }
}

// ---------------- Output projection: grid (32, 8), n-split 96 --------------
__global__ void __launch_bounds__(256, 2)
oproj_mma(float* __restrict__ out)
{
    extern __shared__ __align__(16) char smc[];
    const uint32_t sb = smem_u32(smc);
    const int m0 = blockIdx.x * 256, n0g = blockIdx.y * 96;
    const int tid = threadIdx.x, lane = tid & 31, w = tid >> 5;
    const int WM = (w >> 1) * 64, WN = (w & 1) * 48;

    float acc[4][6][4];
    #pragma unroll
    for (int mt = 0; mt < 4; mt++)
        #pragma unroll
        for (int nt = 0; nt < 6; nt++)
            #pragma unroll
            for (int c = 0; c < 4; c++) acc[mt][nt][c] = 0.0f;

    gemm_main(sb, tid, lane, WM, WN,
              g_Ah + (size_t)m0*DM, g_W2Th + (size_t)n0g*DM, acc);

    #pragma unroll
    for (int mt = 0; mt < 4; mt++)
        #pragma unroll
        for (int rh = 0; rh < 2; rh++) {
            int m = m0 + WM + mt*16 + (lane >> 2) + rh*8;
            #pragma unroll
            for (int nt = 0; nt < 6; nt++) {
                int col = n0g + WN + nt*8 + (lane & 3)*2;
                float2 v;
                v.x = acc[mt][nt][rh*2 + 0] + g_b2[col];
                v.y = acc[mt][nt][rh*2 + 1] + g_b2[col + 1];
                *(float2*)(out + (size_t)m*DM + col) = v;
            }
        }
}

// ======================= Flash attention (unchanged) =======================
#define FQH 0u
#define FKH(s) (18432u + (uint32_t)(s)*35840u)
#define FVH(s) (FKH(s) + 18432u)
#define FL2 125952u
#define F_SMEM 126976

__device__ __forceinline__ void flash_load_kv(uint32_t sb, int s, int kt, int tid,
                                              const __half* Kh, const __half* VTh)
{
    const __half* Khc = Kh + (size_t)kt*128*HD;
    #pragma unroll
    for (int i = 0; i < 2; i++) {
        int f = tid + i*512, r = f >> 3, c = (f & 7) * 8;
        cp16(sb + FKH(s) + (uint32_t)(r*144 + c*2), Khc + (size_t)r*HD + c);
    }
    #pragma unroll
    for (int i = 0; i < 2; i++) {
        int f = tid + i*512, e = f >> 4, c = (f & 15) * 8;
        cp16(sb + FVH(s) + (uint32_t)(e*272 + c*2), VTh + (size_t)e*TT + kt*128 + c);
    }
}

__global__ void __launch_bounds__(512)
flash_mma()
{
    extern __shared__ __align__(16) char smc[];
    const uint32_t sb = smem_u32(smc);
    const int qt = blockIdx.x, bhid = blockIdx.y;
    const int tid = threadIdx.x, lane = tid & 31, w = tid >> 5;
    const int WM = (w >> 1) * 16, wn = w & 1;

    const __half* Qh = g_Qh + ((size_t)bhid*TT + qt*128)*HD;
    const __half* Kh = g_Kh + (size_t)bhid*TT*HD;
    const __half* VTh = g_VTh + (size_t)bhid*HD*TT;

    {
        int f = tid, r = f >> 3, c = (f & 7) * 8;
        cp16(sb + FQH + (uint32_t)(r*144 + c*2), Qh + (size_t)r*HD + c);
        f = tid + 512; r = f >> 3; c = (f & 7) * 8;
        cp16(sb + FQH + (uint32_t)(r*144 + c*2), Qh + (size_t)r*HD + c);
    }
    flash_load_kv(sb, 0, 0, tid, Kh, VTh);
    CP_COMMIT();
    flash_load_kv(sb, 1, 1, tid, Kh, VTh);
    CP_COMMIT();

    float oacc[8][4];
    float lreg[2];
    uint32_t qh[4][4];
    #pragma unroll
    for (int nt = 0; nt < 8; nt++)
        #pragma unroll
        for (int c = 0; c < 4; c++) oacc[nt][c] = 0.0f;
    lreg[0] = 0.0f; lreg[1] = 0.0f;

    int sidx = 0;
    #pragma unroll 1
    for (int kt = 0; kt < 16; kt++) {
        CP_WAIT1();
        __syncthreads();
        if (kt + 2 < 16) {
            int sn = sidx + 2; if (sn >= 3) sn -= 3;
            flash_load_kv(sb, sn, kt+2, tid, Kh, VTh);
            CP_COMMIT();
        }
        const int s = sidx;

        if (kt == 0) {
            #pragma unroll
            for (int ks = 0; ks < 4; ks++)
                lda_frag(qh[ks], sb + FQH, WM, ks*16, 72, lane);
        }

        float sacc[8][4];
        #pragma unroll
        for (int nt = 0; nt < 8; nt++)
            #pragma unroll
            for (int c = 0; c < 4; c++) sacc[nt][c] = 0.0f;
        #pragma unroll
        for (int ks = 0; ks < 4; ks++) {
            int kk = ks * 16;
            uint32_t bhf[4][4];
            #pragma unroll
            for (int np = 0; np < 4; np++)
                ldb_frag2(bhf[np], sb + FKH(s), wn*64 + np*16, kk, 72, lane);
            #pragma unroll
            for (int np = 0; np < 4; np++)
                #pragma unroll
                for (int hp = 0; hp < 2; hp++)
                    mma16816(sacc[np*2+hp], qh[ks], bhf[np] + hp*2);
        }

        #pragma unroll
        for (int ks = 0; ks < 4; ks++) {
            uint32_t pa[4];
            #pragma unroll
            for (int half = 0; half < 2; half++) {
                int nt = ks*2 + half;
                float p0 = fexp2(sacc[nt][0]);
                float p1 = fexp2(sacc[nt][1]);
                float p2 = fexp2(sacc[nt][2]);
                float p3 = fexp2(sacc[nt][3]);
                lreg[0] += p0 + p1;
                lreg[1] += p2 + p3;
                pa[half*2 + 0] = h2pack(p0, p1);
                pa[half*2 + 1] = h2pack(p2, p3);
            }
            #pragma unroll
            for (int np = 0; np < 4; np++) {
                uint32_t vb[4];
                ldb_frag2(vb, sb + FVH(s), np*16, wn*64 + ks*16, 136, lane);
                mma16816(oacc[np*2+0], pa, vb);
                mma16816(oacc[np*2+1], pa, vb + 2);
            }
        }
        if (++sidx >= 3) sidx = 0;
    }
    __syncthreads();

    float* l2r = (float*)(smc + FL2);
    {
        float v0 = lreg[0], v1 = lreg[1];
        v0 += __shfl_xor_sync(0xffffffffu, v0, 1);
        v0 += __shfl_xor_sync(0xffffffffu, v0, 2);
        v1 += __shfl_xor_sync(0xffffffffu, v1, 1);
        v1 += __shfl_xor_sync(0xffffffffu, v1, 2);
        if ((lane & 3) == 0) {
            if (wn == 0) {
                l2r[WM + (lane >> 2)]     = v0;
                l2r[WM + (lane >> 2) + 8] = v1;
            }
        }
        __syncthreads();
        if ((lane & 3) == 0 && wn == 1) {
            atomicAdd(&l2r[WM + (lane >> 2)],     v0);
            atomicAdd(&l2r[WM + (lane >> 2) + 8], v1);
        }
    }

    float* plane = (float*)(smc + (uint32_t)wn * 32768u);
    #pragma unroll
    for (int nt = 0; nt < 8; nt++)
        #pragma unroll
        for (int rh = 0; rh < 2; rh++) {
            int row = WM + (lane >> 2) + rh*8;
            int e = nt*8 + (lane & 3)*2;
            *(float2*)(plane + row*64 + e) = make_float2(oacc[nt][rh*2], oacc[nt][rh*2+1]);
        }
    __syncthreads();

    const int b = bhid / NH, h = bhid % NH;
    float* pl0 = (float*)smc;
    float* pl1 = (float*)(smc + 32768u);
    #pragma unroll
    for (int it = 0; it < 8; it++) {
        int idx = tid + it*512;
        int row = idx >> 5, e2 = (idx & 31) * 2;
        float s0 = pl0[row*64 + e2]     + pl1[row*64 + e2];
        float s1 = pl0[row*64 + e2 + 1] + pl1[row*64 + e2 + 1];
        float inv = 1.0f / l2r[row];
        size_t off = ((size_t)(b*TT + qt*128 + row))*DM + h*HD + e2;
        *(__half2*)(g_Ah + off) = __floats2half2_rn(s0 * inv, s1 * inv);
    }
}

// ---------------------------------------------------------------------------
extern "C" void kernel_launch(void* const* d_in, const int* in_sizes, int n_in,
                              void* d_out, int out_size)
{
    const float* X    = (const float*)d_in[0];
    const float* Wq   = (const float*)d_in[1];
    const float* bq   = (const float*)d_in[2];
    const float* Wk   = (const float*)d_in[3];
    const float* bk   = (const float*)d_in[4];
    const float* Wv   = (const float*)d_in[5];
    const float* bv   = (const float*)d_in[6];
    const float* Wo   = (const float*)d_in[7];
    const float* bo   = (const float*)d_in[8];
    const float* gate = (const float*)d_in[9];
    float* out = (float*)d_out;

    static int init = 0;
    if (!init) {
        cudaFuncSetAttribute(qkv_mma,   cudaFuncAttributeMaxDynamicSharedMemorySize, G_SMEM);
        cudaFuncSetAttribute(oproj_mma, cudaFuncAttributeMaxDynamicSharedMemorySize, G_SMEM);
        cudaFuncSetAttribute(flash_mma, cudaFuncAttributeMaxDynamicSharedMemorySize, F_SMEM);
        init = 1;
    }

    prep_all<<<PB_TOT, 256>>>(X, Wq, Wk, Wv, Wo, bo, gate);
    qkv_mma<<<dim3(MTOT/256, NH, 2), 256, G_SMEM>>>(bq, bk, bv);
    flash_mma<<<dim3(TT/128, NBH), 512, F_SMEM>>>();
    oproj_mma<<<dim3(MTOT/256, DM/96), 256, G_SMEM>>>(out);
}